// round 11
// baseline (speedup 1.0000x reference)
#include <cuda_runtime.h>

static constexpr int H     = 96;
static constexpr int PW2   = 292;         // k_node packed width: 3*96 src + 4 attn scalars
static constexpr int NSG   = H / 4;       // 24 float4 groups per type row
static constexpr int NMAXC = 100000;
static constexpr int TNN   = 128;         // k_node node tile (64 pairs)
static constexpr int TNF   = 64;          // k_final node tile (32 pairs)
static constexpr int SMEMF = 384 * 32 * 8 + 192 * 4;   // xs2 + rden

// ------------------------ device scratch (no allocs allowed) ------------------------
__device__ unsigned long long g_W2d[H * PW2];          // dup-packed node weight (w,w)
__device__ float    g_C[3 * H];                        // per-type constant c_t
__device__ __align__(128) float4 g_src4[(size_t)3 * NMAXC * NSG];  // src-half, 384B rows
__device__ float4   g_attn[NMAXC];                     // (a_s0, a_d0, a_s1, a_d1)
__device__ float4   g_acc4[(size_t)3 * NMAXC * NSG];   // scatter accumulators
__device__ float    g_den[3 * NMAXC];                  // softmax denominators / mean counts
__device__ unsigned long long g_Wfd[384 * H];          // dup-packed folded final weight
__device__ float    g_Mneg[3 * H * H];                 // -(Wdst_t @ Wu_t), [t][k][j]

// ------------------------ f32x2 helpers ------------------------
__device__ __forceinline__ void fma2(unsigned long long& c, unsigned long long a, unsigned long long b) {
    asm("fma.rn.f32x2 %0, %1, %2, %0;" : "+l"(c) : "l"(a), "l"(b));
}
__device__ __forceinline__ unsigned long long pk2(float x, float y) {
    unsigned long long r;
    asm("mov.b64 %0, {%1, %2};" : "=l"(r) : "f"(x), "f"(y));
    return r;
}
__device__ __forceinline__ void upk2(float& x, float& y, unsigned long long v) {
    asm("mov.b64 {%0, %1}, %2;" : "=f"(x), "=f"(y) : "l"(v));
}
__device__ __forceinline__ void ldg2x64(unsigned long long& a, unsigned long long& b, const void* p) {
    asm("ld.global.v2.u64 {%0, %1}, [%2];" : "=l"(a), "=l"(b) : "l"(p));
}

// ------------------------ K_prep: W2 dup-pack, c_t, Mneg ------------------------
__global__ void k_prep(const float* __restrict__ Wm0, const float* __restrict__ Wm1,
                       const float* __restrict__ Wm2,
                       const float* __restrict__ bm0, const float* __restrict__ bm1,
                       const float* __restrict__ bm2,
                       const float* __restrict__ ef0, const float* __restrict__ ef1,
                       const float* __restrict__ ef2,
                       const float* __restrict__ Wn0, const float* __restrict__ Wa0,
                       const float* __restrict__ Wn1, const float* __restrict__ Wa1,
                       const float* __restrict__ Wu) {
    const float* Wm[3] = {Wm0, Wm1, Wm2};
    const float* bm[3] = {bm0, bm1, bm2};
    const float* ef[3] = {ef0, ef1, ef2};
    int tid = blockIdx.x * blockDim.x + threadIdx.x;
    int stride = blockDim.x * gridDim.x;

    // ---- W2 dup-packed: src halves + attention fold, [96 x 292] ----
    for (int idx = tid; idx < H * PW2; idx += stride) {
        int k = idx / PW2, c = idx % PW2;
        float v;
        if (c < 288) {
            int t = c / 96, j = c % 96;
            v = Wm[t][k * 96 + j];
        } else {
            int which = c - 288;           // 0:a_s0 1:a_d0 2:a_s1 3:a_d1
            const float* Wn = (which < 2) ? Wn0 : Wn1;
            const float* Wa = (which < 2) ? Wa0 : Wa1;
            int off = (which & 1) * 32;
            float s = 0.f;
            #pragma unroll
            for (int j = 0; j < 32; j++) s += Wn[k * 32 + j] * Wa[off + j];
            v = s;
        }
        g_W2d[idx] = pk2(v, v);
    }
    // ---- c_t[j] = bm_t[j] + ef_t . Wm_t[192:208, j] ----
    for (int idx = tid; idx < 3 * H; idx += stride) {
        int t = idx / 96, j = idx % 96;
        float s = bm[t][j];
        #pragma unroll
        for (int i = 0; i < 16; i++) s += ef[t][i] * Wm[t][(192 + i) * 96 + j];
        g_C[idx] = s;
    }
    // ---- Mneg[t][k][j] = -(Wdst_t @ Wu_t)[k][j] ----
    for (int idx = tid; idx < 3 * H * H; idx += stride) {
        int t = idx / (96 * 96), r = idx % (96 * 96);
        int k = r / 96, j = r % 96;
        const float* wm = Wm[t];
        float s = 0.f;
        #pragma unroll 8
        for (int i = 0; i < 96; i++)
            s += wm[(96 + k) * 96 + i] * Wu[(96 + 96 * t + i) * 96 + j];
        g_Mneg[(t * 96 + k) * 96 + j] = -s;
    }
}

// ------------------------ K_prep2: folded final weight from Mneg ------------------------
__global__ void k_prep2(const float* __restrict__ Wu) {
    int tid = blockIdx.x * blockDim.x + threadIdx.x;
    int stride = blockDim.x * gridDim.x;
    for (int idx = tid; idx < 384 * H; idx += stride) {
        int k = idx / 96, j = idx % 96;
        float v = Wu[k * 96 + j];
        if (k < 96) {
            v -= g_Mneg[(0 * 96 + k) * 96 + j];
            v -= g_Mneg[(1 * 96 + k) * 96 + j];
            v -= g_Mneg[(2 * 96 + k) * 96 + j];
        }
        g_Wfd[idx] = pk2(v, v);
    }
}

// ------------------------ K_init: zero accumulators ------------------------
__global__ void k_init(int N) {
    int tid = blockIdx.x * blockDim.x + threadIdx.x;
    int stride = blockDim.x * gridDim.x;
    int accq = 3 * N * NSG;
    float4 z4 = make_float4(0.f, 0.f, 0.f, 0.f);
    for (int i = tid; i < accq; i += stride) g_acc4[i] = z4;
    for (int i = tid; i < 3 * N; i += stride) g_den[i] = 0.f;
}

// ------------------------ K_node: [N x 96] @ [96 x 292], node-pair packed f32x2 ------------------------
__global__ void __launch_bounds__(256) k_node(const float* __restrict__ h, int N) {
    __shared__ unsigned long long hs2[H * (TNN / 2)];   // [k][pair], 48KB
    int n0 = blockIdx.x * TNN;
    int tid = threadIdx.x;
    float* hsf = (float*)hs2;

    // stage h into pair layout: hs2[k][p] = (h[n0+2p][k], h[n0+2p+1][k])
    for (int idx = tid; idx < TNN * NSG; idx += 256) {
        int n = idx / NSG, c4 = idx % NSG;
        float4 v = make_float4(0.f, 0.f, 0.f, 0.f);
        if (n0 + n < N) v = ((const float4*)h)[(size_t)(n0 + n) * NSG + c4];
        int p = n >> 1, ln = n & 1;
        hsf[((c4 * 4 + 0) * (TNN / 2) + p) * 2 + ln] = v.x;
        hsf[((c4 * 4 + 1) * (TNN / 2) + p) * 2 + ln] = v.y;
        hsf[((c4 * 4 + 2) * (TNN / 2) + p) * 2 + ln] = v.z;
        hsf[((c4 * 4 + 3) * (TNN / 2) + p) * 2 + ln] = v.w;
    }
    __syncthreads();

    for (int task = tid; task < 73 * (TNN / 8); task += 256) {
        int cg = task % 73;                 // column group (4 cols)
        int p0 = (task / 73) * 4;           // 4 pairs = 8 nodes
        const unsigned long long* Wp = g_W2d + cg * 4;

        unsigned long long acc[4][4];
        #pragma unroll
        for (int p = 0; p < 4; p++)
            #pragma unroll
            for (int c = 0; c < 4; c++) acc[p][c] = 0ull;

        #pragma unroll 4
        for (int k = 0; k < H; k++) {
            unsigned long long w0, w1, w2, w3;
            ldg2x64(w0, w1, Wp + (size_t)k * PW2);
            ldg2x64(w2, w3, Wp + (size_t)k * PW2 + 2);
            ulonglong2 h01 = *(const ulonglong2*)&hs2[k * (TNN / 2) + p0];
            ulonglong2 h23 = *(const ulonglong2*)&hs2[k * (TNN / 2) + p0 + 2];
            unsigned long long hp[4] = {h01.x, h01.y, h23.x, h23.y};
            #pragma unroll
            for (int p = 0; p < 4; p++) {
                fma2(acc[p][0], hp[p], w0);
                fma2(acc[p][1], hp[p], w1);
                fma2(acc[p][2], hp[p], w2);
                fma2(acc[p][3], hp[p], w3);
            }
        }

        #pragma unroll
        for (int p = 0; p < 4; p++) {
            int nA = n0 + (p0 + p) * 2;
            int nB = nA + 1;
            float4 vA, vB;
            upk2(vA.x, vB.x, acc[p][0]);
            upk2(vA.y, vB.y, acc[p][1]);
            upk2(vA.z, vB.z, acc[p][2]);
            upk2(vA.w, vB.w, acc[p][3]);
            if (cg < 72) {
                int t = cg / NSG, off = cg % NSG;
                if (nA < N) g_src4[((size_t)t * N + nA) * NSG + off] = vA;
                if (nB < N) g_src4[((size_t)t * N + nB) * NSG + off] = vB;
            } else {
                if (nA < N) g_attn[nA] = vA;
                if (nB < N) g_attn[nB] = vB;
            }
        }
    }
}

// ------------------------ K_scatter: 4 edges per warp, batched-MLP gather/red ------------------------
__global__ void __launch_bounds__(256) k_scatter(
        const int* __restrict__ src0, const int* __restrict__ dst0,
        const int* __restrict__ src1, const int* __restrict__ dst1,
        const int* __restrict__ src2, const int* __restrict__ dst2,
        int E, int N) {
    const unsigned FULL = 0xffffffffu;
    int gw   = (blockIdx.x * blockDim.x + threadIdx.x) >> 5;
    int lane = threadIdx.x & 31;
    int wpt  = (E + 3) >> 2;
    if (gw >= 3 * wpt) return;
    int t  = gw / wpt;
    int e0 = (gw - t * wpt) * 4;

    const int* sp = (t == 0) ? src0 : (t == 1) ? src1 : src2;
    const int* dp = (t == 0) ? dst0 : (t == 1) ? dst1 : dst2;
    const float4* sb = g_src4 + (size_t)t * N * NSG;
    float4* ab = g_acc4 + (size_t)t * N * NSG;

    int idx = 0;
    if (lane < 8) {
        int e = e0 + (lane & 3);
        if (e < E) idx = (lane < 4) ? sp[e] : dp[e];
    }
    int dsh = __shfl_down_sync(FULL, idx, 4);

    float w = 1.f;
    if (lane < 4 && e0 + lane < E) {
        if (t < 2) {
            float4 as = g_attn[idx];
            float4 ad = g_attn[dsh];
            float x  = t ? (as.z + ad.w) : (as.x + ad.y);
            float sc = (x > 0.f) ? x : 0.01f * x;
            w = __expf(sc);
        }
        atomicAdd(&g_den[t * N + dsh], w);
    }

    float4 v[4];
    int    dj[4];
    float  wj[4];
    #pragma unroll
    for (int j = 0; j < 4; j++) {
        int s  = __shfl_sync(FULL, idx, j);
        dj[j]  = __shfl_sync(FULL, idx, 4 + j);
        wj[j]  = __shfl_sync(FULL, w, j);
        if (lane < 24 && e0 + j < E)
            v[j] = sb[(size_t)s * NSG + lane];
    }
    #pragma unroll
    for (int j = 0; j < 4; j++) {
        if (lane < 24 && e0 + j < E) {
            float4* a = &ab[(size_t)dj[j] * NSG + lane];
            float ww = wj[j];
            asm volatile("red.global.add.v4.f32 [%0], {%1,%2,%3,%4};"
                         :: "l"(a), "f"(v[j].x * ww), "f"(v[j].y * ww),
                            "f"(v[j].z * ww), "f"(v[j].w * ww)
                         : "memory");
        }
    }
}

// ------------------------ K_final: assemble + [N x 384] @ [384 x 96], pair-packed ------------------------
__global__ void __launch_bounds__(192) k_final(const float* __restrict__ h,
                                               const float* __restrict__ bu,
                                               float* __restrict__ out, int N) {
    extern __shared__ unsigned long long dyn[];
    unsigned long long* xs2 = dyn;                      // [384][32 pairs]
    float* rden = (float*)(dyn + 384 * (TNF / 2));      // [64][3]
    float* xsf = (float*)xs2;
    int n0 = blockIdx.x * TNF;
    int tid = threadIdx.x;
    const float* g_acc = (const float*)g_acc4;

    if (tid < TNF * 3) {
        int n = tid / 3, t = tid % 3;
        float den = (n0 + n < N) ? g_den[t * N + n0 + n] : 1.f;
        rden[n * 3 + t] = (den > 0.f) ? 1.0f / den : 0.f;
    }
    __syncthreads();

    // assemble x into pair layout: xs2[c][p] = (x[2p][c], x[2p+1][c])
    for (int ep = tid; ep < TNF * 384; ep += 192) {
        int n = ep / 384, c = ep % 384;
        int gn = n0 + n;
        float v = 0.f;
        if (gn < N) {
            if (c < 96) {
                v = h[(size_t)gn * 96 + c];
            } else {
                int t = (c - 96) / 96, j = (c - 96) % 96;
                float rd = rden[n * 3 + t];
                if (rd > 0.f) {
                    float accv = g_acc[((size_t)t * N + gn) * H + j];
                    v = fmaf(accv, rd, g_C[t * 96 + j]);
                }
            }
        }
        xsf[(c * (TNF / 2) + (n >> 1)) * 2 + (n & 1)] = v;
    }
    __syncthreads();

    {
        int cg = tid % 24;
        int p0 = (tid / 24) * 4;
        const unsigned long long* Wp = g_Wfd + cg * 4;
        float4 b = ((const float4*)bu)[cg];

        unsigned long long acc[4][4];
        #pragma unroll
        for (int p = 0; p < 4; p++) {
            acc[p][0] = pk2(b.x, b.x);
            acc[p][1] = pk2(b.y, b.y);
            acc[p][2] = pk2(b.z, b.z);
            acc[p][3] = pk2(b.w, b.w);
        }

        #pragma unroll 4
        for (int k = 0; k < 384; k++) {
            unsigned long long w0, w1, w2, w3;
            ldg2x64(w0, w1, Wp + (size_t)k * H);
            ldg2x64(w2, w3, Wp + (size_t)k * H + 2);
            ulonglong2 h01 = *(const ulonglong2*)&xs2[k * (TNF / 2) + p0];
            ulonglong2 h23 = *(const ulonglong2*)&xs2[k * (TNF / 2) + p0 + 2];
            unsigned long long hp[4] = {h01.x, h01.y, h23.x, h23.y};
            #pragma unroll
            for (int p = 0; p < 4; p++) {
                fma2(acc[p][0], hp[p], w0);
                fma2(acc[p][1], hp[p], w1);
                fma2(acc[p][2], hp[p], w2);
                fma2(acc[p][3], hp[p], w3);
            }
        }

        #pragma unroll
        for (int p = 0; p < 4; p++) {
            int lnA = (p0 + p) * 2;
            int nA = n0 + lnA, nB = nA + 1;
            float4 vA, vB;
            upk2(vA.x, vB.x, acc[p][0]);
            upk2(vA.y, vB.y, acc[p][1]);
            upk2(vA.z, vB.z, acc[p][2]);
            upk2(vA.w, vB.w, acc[p][3]);
            // rare empty-mailbox correction: add h @ Mneg_t (subtracts folded dst part)
            #pragma unroll
            for (int sel = 0; sel < 2; sel++) {
                int ln = lnA + sel;
                float4& vv = sel ? vB : vA;
                #pragma unroll
                for (int t = 0; t < 3; t++) {
                    if (rden[ln * 3 + t] == 0.f) {
                        float c0 = 0.f, c1 = 0.f, c2 = 0.f, c3 = 0.f;
                        const float* Mp = g_Mneg + (size_t)t * H * H + cg * 4;
                        for (int k = 0; k < H; k++) {
                            float hv = xsf[(k * (TNF / 2) + (ln >> 1)) * 2 + (ln & 1)];
                            float4 m = *(const float4*)(Mp + (size_t)k * H);
                            c0 = fmaf(hv, m.x, c0); c1 = fmaf(hv, m.y, c1);
                            c2 = fmaf(hv, m.z, c2); c3 = fmaf(hv, m.w, c3);
                        }
                        vv.x += c0; vv.y += c1; vv.z += c2; vv.w += c3;
                    }
                }
            }
            vA.x = fmaxf(vA.x, 0.f); vA.y = fmaxf(vA.y, 0.f);
            vA.z = fmaxf(vA.z, 0.f); vA.w = fmaxf(vA.w, 0.f);
            vB.x = fmaxf(vB.x, 0.f); vB.y = fmaxf(vB.y, 0.f);
            vB.z = fmaxf(vB.z, 0.f); vB.w = fmaxf(vB.w, 0.f);
            if (nA < N) ((float4*)out)[(size_t)nA * 24 + cg] = vA;
            if (nB < N) ((float4*)out)[(size_t)nB * 24 + cg] = vB;
        }
    }
}

// ------------------------ launch ------------------------
extern "C" void kernel_launch(void* const* d_in, const int* in_sizes, int n_in,
                              void* d_out, int out_size) {
    const float* h    = (const float*)d_in[0];
    const int*   src0 = (const int*)d_in[1];
    const int*   dst0 = (const int*)d_in[2];
    const int*   src1 = (const int*)d_in[3];
    const int*   dst1 = (const int*)d_in[4];
    const int*   src2 = (const int*)d_in[5];
    const int*   dst2 = (const int*)d_in[6];
    const float* Wm0  = (const float*)d_in[7];
    const float* bm0  = (const float*)d_in[8];
    const float* ef0  = (const float*)d_in[9];
    const float* Wm1  = (const float*)d_in[10];
    const float* bm1  = (const float*)d_in[11];
    const float* ef1  = (const float*)d_in[12];
    const float* Wm2  = (const float*)d_in[13];
    const float* bm2  = (const float*)d_in[14];
    const float* ef2  = (const float*)d_in[15];
    const float* Wn0  = (const float*)d_in[16];
    const float* Wa0  = (const float*)d_in[17];
    const float* Wn1  = (const float*)d_in[18];
    const float* Wa1  = (const float*)d_in[19];
    const float* Wu   = (const float*)d_in[20];
    const float* bu   = (const float*)d_in[21];

    int N = in_sizes[0] / H;
    int E = in_sizes[1];

    static bool attr_set = false;
    if (!attr_set) {
        cudaFuncSetAttribute(k_final, cudaFuncAttributeMaxDynamicSharedMemorySize, SMEMF);
        attr_set = true;
    }

    k_prep<<<192, 256>>>(Wm0, Wm1, Wm2, bm0, bm1, bm2, ef0, ef1, ef2,
                         Wn0, Wa0, Wn1, Wa1, Wu);
    k_prep2<<<48, 256>>>(Wu);
    k_init<<<1024, 256>>>(N);
    k_node<<<(N + TNN - 1) / TNN, 256>>>(h, N);
    int wpt = (E + 3) / 4;
    long warps = 3L * wpt;
    k_scatter<<<(unsigned)((warps + 7) / 8), 256>>>(src0, dst0, src1, dst1, src2, dst2, E, N);
    k_final<<<(N + TNF - 1) / TNF, 192, SMEMF>>>(h, bu, (float*)d_out, N);
}

// round 12
// speedup vs baseline: 1.4472x; 1.4472x over previous
#include <cuda_runtime.h>

static constexpr int H    = 96;
static constexpr int PW2  = 292;          // k_node packed width: 3*96 src + 4 attn scalars
static constexpr int NCG2 = PW2 / 4;      // 73 float4 groups
static constexpr int NSG  = H / 4;        // 24 float4 groups per type row
static constexpr int NMAXC = 100000;

// ------------------------ device scratch (no allocs allowed) ------------------------
__device__ float4   g_W2[H * NCG2];                    // packed node weight [k][col/4]
__device__ float    g_C[3 * H];                        // per-type constant c_t
__device__ __align__(128) float4 g_src4[(size_t)3 * NMAXC * NSG];  // src-half, 384B rows
__device__ float4   g_attn[NMAXC];                     // (a_s0, a_d0, a_s1, a_d1)
__device__ float4   g_acc4[(size_t)3 * NMAXC * NSG];   // scatter accumulators
__device__ float    g_den[3 * NMAXC];                  // softmax denominators / mean counts
__device__ float4   g_Wf[384 * NSG];                   // folded final weight [k][j/4]
__device__ float4   g_Mneg[3 * H * NSG];               // -(Wdst_t @ Wu_t), [t][k][j/4]

// ------------------------ f32x2 helpers ------------------------
__device__ __forceinline__ void fma2(unsigned long long& c, unsigned long long a, unsigned long long b) {
    asm("fma.rn.f32x2 %0, %1, %2, %0;" : "+l"(c) : "l"(a), "l"(b));
}
__device__ __forceinline__ unsigned long long pk2(float x, float y) {
    unsigned long long r;
    asm("mov.b64 %0, {%1, %2};" : "=l"(r) : "f"(x), "f"(y));
    return r;
}
__device__ __forceinline__ void upk2(float& x, float& y, unsigned long long v) {
    asm("mov.b64 {%0, %1}, %2;" : "=f"(x), "=f"(y) : "l"(v));
}
__device__ __forceinline__ void ldg2x64(unsigned long long& a, unsigned long long& b, const void* p) {
    asm("ld.global.v2.u64 {%0, %1}, [%2];" : "=l"(a), "=l"(b) : "l"(p));
}
__device__ __forceinline__ void stg2x64(void* p, unsigned long long a, unsigned long long b) {
    asm("st.global.v2.u64 [%0], {%1, %2};" :: "l"(p), "l"(a), "l"(b) : "memory");
}

// ------------------------ K_prep: pack weights, fold dst-half, zero accumulators ------------------------
__global__ void k_prep(const float* __restrict__ Wm0, const float* __restrict__ Wm1,
                       const float* __restrict__ Wm2,
                       const float* __restrict__ bm0, const float* __restrict__ bm1,
                       const float* __restrict__ bm2,
                       const float* __restrict__ ef0, const float* __restrict__ ef1,
                       const float* __restrict__ ef2,
                       const float* __restrict__ Wn0, const float* __restrict__ Wa0,
                       const float* __restrict__ Wn1, const float* __restrict__ Wa1,
                       const float* __restrict__ Wu, int N) {
    const float* Wm[3] = {Wm0, Wm1, Wm2};
    const float* bm[3] = {bm0, bm1, bm2};
    const float* ef[3] = {ef0, ef1, ef2};
    int tid = blockIdx.x * blockDim.x + threadIdx.x;
    int stride = blockDim.x * gridDim.x;

    // ---- zero accumulators (folded former k_init) ----
    {
        int accq = 3 * N * NSG;
        float4 z4 = make_float4(0.f, 0.f, 0.f, 0.f);
        for (int i = tid; i < accq; i += stride) g_acc4[i] = z4;
        for (int i = tid; i < 3 * N; i += stride) g_den[i] = 0.f;
    }

    // ---- W2: src halves + attention fold, [96 x 292] ----
    float* W2 = (float*)g_W2;
    for (int idx = tid; idx < H * PW2; idx += stride) {
        int k = idx / PW2, c = idx % PW2;
        float v;
        if (c < 288) {                     // src-half rows [0:96) of Wm_t
            int t = c / 96, j = c % 96;
            v = Wm[t][k * 96 + j];
        } else {                           // folded attention vectors Wn @ Wa-half
            int which = c - 288;           // 0:a_s0 1:a_d0 2:a_s1 3:a_d1
            const float* Wn = (which < 2) ? Wn0 : Wn1;
            const float* Wa = (which < 2) ? Wa0 : Wa1;
            int off = (which & 1) * 32;
            float s = 0.f;
            #pragma unroll
            for (int j = 0; j < 32; j++) s += Wn[k * 32 + j] * Wa[off + j];
            v = s;
        }
        W2[idx] = v;
    }
    // ---- c_t[j] = bm_t[j] + ef_t . Wm_t[192:208, j] ----
    for (int idx = tid; idx < 3 * H; idx += stride) {
        int t = idx / 96, j = idx % 96;
        float s = bm[t][j];
        #pragma unroll
        for (int i = 0; i < 16; i++) s += ef[t][i] * Wm[t][(192 + i) * 96 + j];
        g_C[idx] = s;
    }
    // ---- Wf[k][j]: k<96 -> Wu_h + sum_t Wdst_t@Wu_t ; k>=96 -> Wu row ----
    float* Wf = (float*)g_Wf;
    for (int idx = tid; idx < 384 * H; idx += stride) {
        int k = idx / 96, j = idx % 96;
        float v = Wu[k * 96 + j];
        if (k < 96) {
            #pragma unroll
            for (int t = 0; t < 3; t++) {
                const float* wm = Wm[t];
                float s = 0.f;
                #pragma unroll 8
                for (int i = 0; i < 96; i++)
                    s += wm[(96 + k) * 96 + i] * Wu[(96 + 96 * t + i) * 96 + j];
                v += s;
            }
        }
        Wf[k * 96 + j] = v;
    }
    // ---- Mneg[t][k][j] = -(Wdst_t @ Wu_t)[k][j]  (empty-node correction) ----
    float* Mn = (float*)g_Mneg;
    for (int idx = tid; idx < 3 * H * H; idx += stride) {
        int t = idx / (96 * 96), r = idx % (96 * 96);
        int k = r / 96, j = r % 96;
        const float* wm = Wm[t];
        float s = 0.f;
        #pragma unroll 8
        for (int i = 0; i < 96; i++)
            s += wm[(96 + k) * 96 + i] * Wu[(96 + 96 * t + i) * 96 + j];
        Mn[(t * 96 + k) * 96 + j] = -s;
    }
}

// ------------------------ K_node: packed GEMM [N x 96] @ [96 x 292] ------------------------
// Register-tiled: 8 nodes per thread per W column-group, f32x2 packed FMA.
static constexpr int TN = 64;              // node tile
__global__ void __launch_bounds__(256) k_node(const float* __restrict__ h, int N) {
    __shared__ unsigned long long hs2[TN * H];   // 48KB
    int n0 = blockIdx.x * TN;
    int tid = threadIdx.x;

    for (int idx = tid; idx < TN * (H / 4); idx += 256) {   // 1536 float4
        int n = idx / (H / 4);
        int c4 = idx % (H / 4);
        float4 v = make_float4(0.f, 0.f, 0.f, 0.f);
        if (n0 + n < N) v = ((const float4*)h)[(size_t)(n0 + n) * (H / 4) + c4];
        int base = n * H + c4 * 4;
        hs2[base + 0] = pk2(v.x, v.x);
        hs2[base + 1] = pk2(v.y, v.y);
        hs2[base + 2] = pk2(v.z, v.z);
        hs2[base + 3] = pk2(v.w, v.w);
    }
    __syncthreads();

    for (int task = tid; task < NCG2 * (TN / 8); task += 256) {
        int cg = task % NCG2;              // adjacent threads -> adjacent cg (coalesced W)
        int nb = (task / NCG2) * 8;        // node sub-tile base
        const float4* Wp = g_W2 + cg;
        const unsigned long long* hp = &hs2[nb * H];

        unsigned long long a0[8], a1[8];
        #pragma unroll
        for (int i = 0; i < 8; i++) { a0[i] = 0ull; a1[i] = 0ull; }

        #pragma unroll 4
        for (int k = 0; k < H; k++) {
            unsigned long long w0, w1;
            ldg2x64(w0, w1, Wp + (size_t)k * NCG2);
            #pragma unroll
            for (int i = 0; i < 8; i++) {
                unsigned long long hh = hp[i * H + k];   // LDS.64 broadcast
                fma2(a0[i], hh, w0);
                fma2(a1[i], hh, w1);
            }
        }

        if (cg < 72) {
            int t = cg / NSG, off = cg % NSG;
            #pragma unroll
            for (int i = 0; i < 8; i++) {
                int n = n0 + nb + i;
                if (n < N)
                    stg2x64(&g_src4[((size_t)t * N + n) * NSG + off], a0[i], a1[i]);
            }
        } else {                            // cg==72: attention scalars (cols 288-291)
            #pragma unroll
            for (int i = 0; i < 8; i++) {
                int n = n0 + nb + i;
                if (n < N) stg2x64(&g_attn[n], a0[i], a1[i]);
            }
        }
    }
}

// ------------------------ K_scatter: 4 edges per warp, batched-MLP gather/red ------------------------
// No max-subtraction: scores ~N(0,1), exp() safe in fp32; exp(s)/sum(exp(s)) identical to shifted form.
__global__ void __launch_bounds__(256) k_scatter(
        const int* __restrict__ src0, const int* __restrict__ dst0,
        const int* __restrict__ src1, const int* __restrict__ dst1,
        const int* __restrict__ src2, const int* __restrict__ dst2,
        int E, int N) {
    const unsigned FULL = 0xffffffffu;
    int gw   = (blockIdx.x * blockDim.x + threadIdx.x) >> 5;
    int lane = threadIdx.x & 31;
    int wpt  = (E + 3) >> 2;               // warps per edge type
    if (gw >= 3 * wpt) return;
    int t  = gw / wpt;
    int e0 = (gw - t * wpt) * 4;

    const int* sp = (t == 0) ? src0 : (t == 1) ? src1 : src2;
    const int* dp = (t == 0) ? dst0 : (t == 1) ? dst1 : dst2;
    const float4* sb = g_src4 + (size_t)t * N * NSG;   // 384B-aligned rows
    float4* ab = g_acc4 + (size_t)t * N * NSG;

    // lanes 0-3 load src[e0+lane], lanes 4-7 load dst[e0+lane-4]  (MLP=8)
    int idx = 0;
    if (lane < 8) {
        int e = e0 + (lane & 3);
        if (e < E) idx = (lane < 4) ? sp[e] : dp[e];
    }
    int dsh = __shfl_down_sync(FULL, idx, 4);   // lanes 0-3: their edge's dst

    // lanes 0-3: per-edge weight (2 random 16B loads each -> warp MLP=8) + den atomic
    float w = 1.f;
    if (lane < 4 && e0 + lane < E) {
        if (t < 2) {
            float4 as = g_attn[idx];
            float4 ad = g_attn[dsh];
            float x  = t ? (as.z + ad.w) : (as.x + ad.y);
            float sc = (x > 0.f) ? x : 0.01f * x;    // leaky_relu(0.01)
            w = __expf(sc);
        }
        atomicAdd(&g_den[t * N + dsh], w);
    }

    // batched gathers: 4 independent LDG.128 chains in flight
    float4 v[4];
    int    dj[4];
    float  wj[4];
    #pragma unroll
    for (int j = 0; j < 4; j++) {
        int s  = __shfl_sync(FULL, idx, j);
        dj[j]  = __shfl_sync(FULL, idx, 4 + j);
        wj[j]  = __shfl_sync(FULL, w, j);
        if (lane < 24 && e0 + j < E)
            v[j] = sb[(size_t)s * NSG + lane];
    }
    #pragma unroll
    for (int j = 0; j < 4; j++) {
        if (lane < 24 && e0 + j < E) {
            float4* a = &ab[(size_t)dj[j] * NSG + lane];
            float ww = wj[j];
            asm volatile("red.global.add.v4.f32 [%0], {%1,%2,%3,%4};"
                         :: "l"(a), "f"(v[j].x * ww), "f"(v[j].y * ww),
                            "f"(v[j].z * ww), "f"(v[j].w * ww)
                         : "memory");
        }
    }
}

// ------------------------ K_final: assemble + fused GEMM [N x 384] @ [384 x 96] (dst-half folded) ------------------------
__global__ void __launch_bounds__(192) k_final(const float* __restrict__ h,
                                               const float* __restrict__ bu,
                                               float* __restrict__ out, int N) {
    __shared__ __align__(16) float xs[32 * 384];    // 48 KB
    __shared__ float rden[32 * 3];
    int n0 = blockIdx.x * 32;
    int tid = threadIdx.x;
    const float* g_acc = (const float*)g_acc4;

    // stage reciprocals once per (node, type); 0 marks an empty mailbox
    if (tid < 96) {
        int n = tid / 3, t = tid % 3;
        float den = (n0 + n < N) ? g_den[t * N + n0 + n] : 1.f;
        rden[n * 3 + t] = (den > 0.f) ? 1.0f / den : 0.f;
    }
    __syncthreads();

    for (int ep = tid; ep < 32 * 384; ep += 192) {
        int n = ep / 384, c = ep % 384;
        int gn = n0 + n;
        float v = 0.f;
        if (gn < N) {
            if (c < 96) {
                v = h[(size_t)gn * 96 + c];
            } else {
                int t = (c - 96) / 96, j = (c - 96) % 96;
                float rd = rden[n * 3 + t];
                if (rd > 0.f) {
                    float accv = g_acc[((size_t)t * N + gn) * H + j];
                    v = fmaf(accv, rd, g_C[t * 96 + j]);
                }
            }
        }
        xs[n * 384 + c] = v;
    }
    __syncthreads();

    {
        int cg = tid % 24;                 // output float4 group (coalesced W)
        int nb = (tid / 24) * 4;           // 4 nodes per thread
        const float4* Wp = g_Wf + cg;
        float4 b = ((const float4*)bu)[cg];

        unsigned long long a0[4], a1[4];
        #pragma unroll
        for (int i = 0; i < 4; i++) { a0[i] = pk2(b.x, b.y); a1[i] = pk2(b.z, b.w); }

        #pragma unroll 4
        for (int k = 0; k < 384; k++) {
            unsigned long long w0, w1;
            ldg2x64(w0, w1, Wp + (size_t)k * 24);
            #pragma unroll
            for (int i = 0; i < 4; i++) {
                float hv = xs[(nb + i) * 384 + k];
                unsigned long long hh = pk2(hv, hv);
                fma2(a0[i], hh, w0);
                fma2(a1[i], hh, w1);
            }
        }

        #pragma unroll
        for (int i = 0; i < 4; i++) {
            int n = n0 + nb + i;
            if (n < N) {
                // rare empty-mailbox correction: add h @ Mneg_t (removes folded dst part)
                #pragma unroll
                for (int t = 0; t < 3; t++) {
                    if (rden[(nb + i) * 3 + t] == 0.f) {
                        const float4* Mp = g_Mneg + (size_t)t * H * 24 + cg;
                        for (int k = 0; k < H; k++) {
                            unsigned long long m0, m1;
                            ldg2x64(m0, m1, Mp + (size_t)k * 24);
                            float hv = xs[(nb + i) * 384 + k];
                            unsigned long long hh = pk2(hv, hv);
                            fma2(a0[i], hh, m0);
                            fma2(a1[i], hh, m1);
                        }
                    }
                }
                float4 r;
                upk2(r.x, r.y, a0[i]);
                upk2(r.z, r.w, a1[i]);
                r.x = fmaxf(r.x, 0.f); r.y = fmaxf(r.y, 0.f);
                r.z = fmaxf(r.z, 0.f); r.w = fmaxf(r.w, 0.f);
                ((float4*)out)[(size_t)n * 24 + cg] = r;
            }
        }
    }
}

// ------------------------ launch ------------------------
extern "C" void kernel_launch(void* const* d_in, const int* in_sizes, int n_in,
                              void* d_out, int out_size) {
    const float* h    = (const float*)d_in[0];
    const int*   src0 = (const int*)d_in[1];
    const int*   dst0 = (const int*)d_in[2];
    const int*   src1 = (const int*)d_in[3];
    const int*   dst1 = (const int*)d_in[4];
    const int*   src2 = (const int*)d_in[5];
    const int*   dst2 = (const int*)d_in[6];
    const float* Wm0  = (const float*)d_in[7];
    const float* bm0  = (const float*)d_in[8];
    const float* ef0  = (const float*)d_in[9];
    const float* Wm1  = (const float*)d_in[10];
    const float* bm1  = (const float*)d_in[11];
    const float* ef1  = (const float*)d_in[12];
    const float* Wm2  = (const float*)d_in[13];
    const float* bm2  = (const float*)d_in[14];
    const float* ef2  = (const float*)d_in[15];
    const float* Wn0  = (const float*)d_in[16];
    const float* Wa0  = (const float*)d_in[17];
    const float* Wn1  = (const float*)d_in[18];
    const float* Wa1  = (const float*)d_in[19];
    const float* Wu   = (const float*)d_in[20];
    const float* bu   = (const float*)d_in[21];

    int N = in_sizes[0] / H;
    int E = in_sizes[1];

    k_prep<<<256, 256>>>(Wm0, Wm1, Wm2, bm0, bm1, bm2, ef0, ef1, ef2,
                         Wn0, Wa0, Wn1, Wa1, Wu, N);
    k_node<<<(N + TN - 1) / TN, 256>>>(h, N);
    int wpt = (E + 3) / 4;
    long warps = 3L * wpt;
    k_scatter<<<(unsigned)((warps + 7) / 8), 256>>>(src0, dst0, src1, dst1, src2, dst2, E, N);
    k_final<<<(N + 31) / 32, 192>>>(h, bu, (float*)d_out, N);
}